// round 1
// baseline (speedup 1.0000x reference)
#include <cuda_runtime.h>
#include <cuda_bf16.h>

// ContinuousEmbedding: x:[64,8192] f32 in [-1,1], emb:[64,128] f32.
// xs = (x+1)*32 ; w_p = hann(xs - p, window=8) (nonzero only for 8 points);
// out = normalize(w) @ emb  -> [64,8192,128] f32.
//
// Per-warp: 32 consecutive x. Per-x: lane l computes dims [4l,4l+4) as float4.
// Embeddings (32KB fp32) staged in shared; 8 conflict-free LDS.128 per x.

#define NUM_POINTS 64
#define OUT_DIMS   128
#define V4_PER_ROW (OUT_DIMS / 4)   // 32 float4 per embedding row

__global__ __launch_bounds__(256, 4)
void ContinuousEmbedding_89412629168402_kernel(const float* __restrict__ x,
                                               const float* __restrict__ emb,
                                               float* __restrict__ out,
                                               int n_x)
{
    __shared__ float4 emb_s[NUM_POINTS * V4_PER_ROW];   // 64*32*16B = 32 KB

    // Stage embedding table (coalesced float4)
    const float4* emb4 = reinterpret_cast<const float4*>(emb);
    #pragma unroll
    for (int i = threadIdx.x; i < NUM_POINTS * V4_PER_ROW; i += 256)
        emb_s[i] = emb4[i];
    __syncthreads();

    const int warp = blockIdx.x * (blockDim.x >> 5) + (threadIdx.x >> 5);
    const int lane = threadIdx.x & 31;
    const int base = warp * 32;
    if (base >= n_x) return;

    float xval = 0.0f;
    if (base + lane < n_x) xval = x[base + lane];

    float4* __restrict__ out4 = reinterpret_cast<float4*>(out);

    const float R = 0.70710678118654752440f;  // sqrt(2)/2
    const int cnt = min(32, n_x - base);

    for (int k = 0; k < cnt; ++k) {
        const float xv = __shfl_sync(0xffffffffu, xval, k);
        // map to grid coords [0, 64]
        const float xs = (xv + 1.0f) * 32.0f;
        const float f  = floorf(xs);
        const int   p_base = (int)f - 3;          // 8-point window p_base..p_base+7
        const float t  = xs - f;                  // in [0,1)

        // w_j = cos^2(pi*d_j/8) = 0.5*(1 + cos(pi*d_j/4)), d_j = t+3-j
        //     = 0.5 + 0.5*cos(a - j*pi/4),  a = (pi/4)*(t+3)
        const float a  = 0.78539816339744830962f * (t + 3.0f);
        const float ca = __cosf(a);
        const float sa = __sinf(a);
        const float hc = 0.5f * ca;
        const float hs = 0.5f * sa;
        const float u  = 0.5f * R * (ca + sa);
        const float v  = 0.5f * R * (sa - ca);

        float w[8];
        w[0] = 0.5f + hc;
        w[1] = 0.5f + u;
        w[2] = 0.5f + hs;
        w[3] = 0.5f + v;
        w[4] = 0.5f - hc;
        w[5] = 0.5f - u;
        w[6] = 0.5f - hs;
        w[7] = 0.5f - v;

        // mask out-of-grid points, accumulate normalizer
        float s = 0.0f;
        #pragma unroll
        for (int j = 0; j < 8; ++j) {
            const int p = p_base + j;
            if (p < 0 || p >= NUM_POINTS) w[j] = 0.0f;
            s += w[j];
        }
        const float inv = (s > 0.0f) ? (1.0f / s) : 0.0f;

        float4 acc = make_float4(0.0f, 0.0f, 0.0f, 0.0f);
        #pragma unroll
        for (int j = 0; j < 8; ++j) {
            const int p = min(max(p_base + j, 0), NUM_POINTS - 1);
            const float4 e = emb_s[p * V4_PER_ROW + lane];
            const float ws = w[j] * inv;
            acc.x = fmaf(ws, e.x, acc.x);
            acc.y = fmaf(ws, e.y, acc.y);
            acc.z = fmaf(ws, e.z, acc.z);
            acc.w = fmaf(ws, e.w, acc.w);
        }

        out4[(size_t)(base + k) * V4_PER_ROW + lane] = acc;
    }
}

extern "C" void kernel_launch(void* const* d_in, const int* in_sizes, int n_in,
                              void* d_out, int out_size)
{
    const float* x   = (const float*)d_in[0];   // [64, 8192] f32
    const float* emb = (const float*)d_in[1];   // [64, 128]  f32
    float* out = (float*)d_out;                 // [64, 8192, 128] f32

    const int n_x = in_sizes[0];                // 524288
    const int warps  = (n_x + 31) / 32;
    const int blocks = (warps + 7) / 8;         // 8 warps (256 threads) per block
    ContinuousEmbedding_89412629168402_kernel<<<blocks, 256>>>(x, emb, out, n_x);
}